// round 1
// baseline (speedup 1.0000x reference)
#include <cuda_runtime.h>

// ISTA deconvolution, fully fused per-row kernel.
// B=4096 rows, L=4096, K=128, T=5 soft-threshold iterations (iteration-invariant
// update => computed once, thresholding fused into epilogue).

#define BDIM 4096
#define LDIM 4096
#define KW   128
#define PADL 63          // (K-1)/2 left zero pad (TF SAME, cross-correlation)
#define NTH  512         // threads per CTA; each thread owns 8 consecutive outputs
#define PL   537         // plane stride in floats (odd, >= 529)
#define LAMBDA 0.1f
#define TITER 5

typedef unsigned long long ull;

__device__ __forceinline__ ull pk2(float lo, float hi) {
    ull r;
    asm("mov.b64 %0, {%1, %2};" : "=l"(r) : "f"(lo), "f"(hi));
    return r;
}
__device__ __forceinline__ void unpk2(ull v, float& lo, float& hi) {
    asm("mov.b64 {%0, %1}, %2;" : "=f"(lo), "=f"(hi) : "l"(v));
}
// Packed dual-FMA: the only way to reach 128 FP32 FMA/cyc/SM on sm_103a.
__device__ __forceinline__ ull fma2(ull a, ull b, ull c) {
    ull d;
    asm("fma.rn.f32x2 %0, %1, %2, %3;" : "=l"(d) : "l"(a), "l"(b), "l"(c));
    return d;
}

// Planar shared layout: logical padded index j lives at sh[(j&7)*PL + (j>>3)].
// For thread tid with base = 8*tid, logical index (8*tid + c) is at
// ((c&7)*PL + (c>>3)) + tid  -> with full unroll, pure immediate offsets,
// same plane + consecutive m across lanes => conflict-free.

// Computes o[r] = sum_k xp[8*tid + r + k] * hk[k], r = 0..7, using a sliding
// register window kept as even-phase and odd-phase f32x2 pair rings.
__device__ __forceinline__ void conv8(const float* __restrict__ sin_,
                                      const ull* __restrict__ hp,
                                      int tid, float* __restrict__ o)
{
#define XLD(c) sin_[(((c) & 7) * PL) + ((c) >> 3) + tid]
    float x0 = XLD(0), x1 = XLD(1), x2 = XLD(2), x3 = XLD(3), x4 = XLD(4),
          x5 = XLD(5), x6 = XLD(6), x7 = XLD(7), x8 = XLD(8);
    ull pe0 = pk2(x0, x1), pe1 = pk2(x2, x3), pe2 = pk2(x4, x5), pe3 = pk2(x6, x7);
    ull po0 = pk2(x1, x2), po1 = pk2(x3, x4), po2 = pk2(x5, x6), po3 = pk2(x7, x8);
    float carry = x8;
    ull a0 = 0ull, a1 = 0ull, a2 = 0ull, a3 = 0ull;  // (0.f,0.f) bit pattern

#pragma unroll
    for (int k = 0; k < KW; k += 2) {
        ull he = hp[k];        // (h[k],   h[k])   pre-duplicated, LDS.64 broadcast
        ull ho = hp[k + 1];    // (h[k+1], h[k+1])
        a0 = fma2(pe0, he, a0);
        a1 = fma2(pe1, he, a1);
        a2 = fma2(pe2, he, a2);
        a3 = fma2(pe3, he, a3);
        a0 = fma2(po0, ho, a0);
        a1 = fma2(po1, ho, a1);
        a2 = fma2(po2, ho, a2);
        a3 = fma2(po3, ho, a3);
        if (k < KW - 2) {
            float xa = XLD(k + 9);
            float xb = XLD(k + 10);
            pe0 = pe1; pe1 = pe2; pe2 = pe3; pe3 = pk2(carry, xa);
            po0 = po1; po1 = po2; po2 = po3; po3 = pk2(xa, xb);
            carry = xb;
        }
    }
    unpk2(a0, o[0], o[1]);
    unpk2(a1, o[2], o[3]);
    unpk2(a2, o[4], o[5]);
    unpk2(a3, o[6], o[7]);
#undef XLD
}

__global__ __launch_bounds__(NTH, 2)
void ista_row_kernel(const float* __restrict__ y,
                     const float* __restrict__ h,
                     const float* __restrict__ step,
                     float* __restrict__ out)
{
    __shared__ __align__(16) float sh_a[8 * PL];   // padded y row (planar)
    __shared__ __align__(16) float sh_b[8 * PL];   // padded residual row (planar)
    __shared__ __align__(16) ull   sh_h[KW];       // (h[k],h[k]) pairs
    __shared__ __align__(16) ull   sh_hr[KW];      // reversed-kernel pairs

    const int tid = threadIdx.x;
    const int row = blockIdx.x;
    const float* yr = y + (long long)row * LDIM;

    // Zero both padded buffers (covers SAME zero-padding + overshoot region).
    for (int i = tid; i < 8 * PL; i += NTH) { sh_a[i] = 0.0f; sh_b[i] = 0.0f; }
    if (tid < KW) {
        float hv = h[tid];
        sh_h[tid] = pk2(hv, hv);
        sh_hr[KW - 1 - tid] = pk2(hv, hv);
    }
    __syncthreads();

    // Load y row into planar padded layout.
    for (int i = tid; i < LDIM; i += NTH) {
        int j = i + PADL;
        sh_a[(j & 7) * PL + (j >> 3)] = yr[i];
    }
    __syncthreads();

    // Stage 1: resid = y - corr_same(y, h)
    {
        float acc[8];
        conv8(sh_a, sh_h, tid, acc);
#pragma unroll
        for (int r = 0; r < 8; r++) {
            const int c = PADL + r;
            const int idx = ((c & 7) * PL) + (c >> 3) + tid;
            float yc = sh_a[idx];
            sh_b[idx] = yc - acc[r];
        }
    }
    __syncthreads();

    // Stage 2: u = corr_same(resid, h_rev); then 5x soft-threshold epilogue.
    {
        float u[8];
        conv8(sh_b, sh_hr, tid, u);
        const float s = step[0];
        float xv[8];
#pragma unroll
        for (int r = 0; r < 8; r++) {
            float su = s * u[r];
            float x = 0.0f;
#pragma unroll
            for (int t = 0; t < TITER; t++) {
                x += su;
                x = copysignf(fmaxf(fabsf(x) - LAMBDA, 0.0f), x);
            }
            xv[r] = x;
        }
        float4* o4 = reinterpret_cast<float4*>(out + (long long)row * LDIM + tid * 8);
        o4[0] = make_float4(xv[0], xv[1], xv[2], xv[3]);
        o4[1] = make_float4(xv[4], xv[5], xv[6], xv[7]);
    }
}

extern "C" void kernel_launch(void* const* d_in, const int* in_sizes, int n_in,
                              void* d_out, int out_size)
{
    const float* y = nullptr;
    const float* h = nullptr;
    const float* s = nullptr;
    for (int i = 0; i < n_in; i++) {
        if (in_sizes[i] == BDIM * LDIM)      y = (const float*)d_in[i];
        else if (in_sizes[i] == KW)          h = (const float*)d_in[i];
        else if (in_sizes[i] == 1)           s = (const float*)d_in[i];
    }
    ista_row_kernel<<<BDIM, NTH>>>(y, h, s, (float*)d_out);
}

// round 2
// speedup vs baseline: 1.8220x; 1.8220x over previous
#include <cuda_runtime.h>

// ISTA deconvolution, fully fused per-row kernel (round 2).
// Key structure: padded row stored in SMEM as two staggered pair arrays
// (even-start pairs and odd-start pairs), each in 8-plane "pair-planar"
// layout so every hot-loop access is a conflict-free LDS.64 straight into
// an f32x2 operand register pair. No packing movs in the main loop.
//
// epairs[p] = (xp[2p],   xp[2p+1])
// opairs[p] = (xp[2p+1], xp[2p+2])
// pair p lives at ull index (p&7)*PPL8 + (p>>3); thread t touches p = 8t + c
// so the address is plane(c&7), offset t + (c>>3): lane-consecutive.
//
// conv pair q (outputs 16t+2q, 16t+2q+1), k = 2m / 2m+1:
//   acc[q] += epairs[8t+q+m] * (h[2m],h[2m])  + opairs[8t+q+m] * (h[2m+1],h[2m+1])
//
// ISTA epilogue closed form: iterating x <- soft(x + su) from x=0 for T steps
// gives exactly x_T = T * sign(su) * max(|su| - lambda, 0).

#define BDIM 4096
#define LDIM 4096
#define KW   128
#define NTH  256
#define PPL8 266                 // ull per plane (needs >= 264)
#define NPAIR_ULL (8 * PPL8)     // 2128 ull per pair array
#define LAMBDA 0.1f
#define TITER  5.0f

typedef unsigned long long ull;

__device__ __forceinline__ ull pk2(float lo, float hi) {
    ull r;
    asm("mov.b64 %0, {%1, %2};" : "=l"(r) : "f"(lo), "f"(hi));
    return r;
}
__device__ __forceinline__ void unpk2(ull v, float& lo, float& hi) {
    asm("mov.b64 {%0, %1}, %2;" : "=f"(lo), "=f"(hi) : "l"(v));
}
__device__ __forceinline__ ull fma2(ull a, ull b, ull c) {
    ull d;
    asm("fma.rn.f32x2 %0, %1, %2, %3;" : "=l"(d) : "l"(a), "l"(b), "l"(c));
    return d;
}

// ull index of pair p = 8t + c inside a pair-planar array.
#define PIDX(c, t) ((((c) & 7) * PPL8) + ((c) >> 3) + (t))

// 16-output convolution over 8 accumulator pairs. Rings E/O of 4+4... (8 slots),
// refill one slot per m; full unroll => static rotation, zero movs.
__device__ __forceinline__ void conv16(const ull* __restrict__ ep,
                                       const ull* __restrict__ op,
                                       const ull* __restrict__ hE,
                                       const ull* __restrict__ hO,
                                       int t, ull* __restrict__ acc)
{
    ull E[8], O[8];
#pragma unroll
    for (int c = 0; c < 8; c++) {
        E[c] = ep[c * PPL8 + t];
        O[c] = op[c * PPL8 + t];
    }
#pragma unroll
    for (int q = 0; q < 8; q++) acc[q] = 0ull;

    ulonglong2 he2 = make_ulonglong2(0, 0), ho2 = make_ulonglong2(0, 0);
#pragma unroll
    for (int m = 0; m < KW / 2; m++) {
        if ((m & 1) == 0) {
            he2 = *reinterpret_cast<const ulonglong2*>(hE + m);
            ho2 = *reinterpret_cast<const ulonglong2*>(hO + m);
        }
        ull hem = (m & 1) ? he2.y : he2.x;
        ull hom = (m & 1) ? ho2.y : ho2.x;
#pragma unroll
        for (int q = 0; q < 8; q++) {
            acc[q] = fma2(E[(m + q) & 7], hem, acc[q]);
            acc[q] = fma2(O[(m + q) & 7], hom, acc[q]);
        }
        if (m < KW / 2 - 1) {
            const int c = m + 8;
            E[m & 7] = ep[PIDX(c, t)];
            O[m & 7] = op[PIDX(c, t)];
        }
    }
}

__global__ __launch_bounds__(NTH, 3)
void ista_row_kernel(const float* __restrict__ y,
                     const float* __restrict__ h,
                     const float* __restrict__ step,
                     float* __restrict__ out)
{
    __shared__ __align__(16) ull sh_ep[NPAIR_ULL];
    __shared__ __align__(16) ull sh_op[NPAIR_ULL];
    __shared__ __align__(16) ull sh_he[KW / 2], sh_ho[KW / 2];
    __shared__ __align__(16) ull sh_re[KW / 2], sh_ro[KW / 2];

    const int t = threadIdx.x;
    const int row = blockIdx.x;
    const float* yr = y + (long long)row * LDIM;
    const float s = __ldg(step);

    // Zero pair arrays (covers SAME zero-padding + overshoot, both stages).
    for (int i = t; i < NPAIR_ULL; i += NTH) { sh_ep[i] = 0ull; sh_op[i] = 0ull; }
    if (t < KW / 2) {
        float a0 = h[2 * t], a1 = h[2 * t + 1];
        sh_he[t] = pk2(a0, a0);
        sh_ho[t] = pk2(a1, a1);
        float b0 = h[KW - 1 - 2 * t], b1 = h[KW - 2 - 2 * t];  // reversed kernel
        sh_re[t] = pk2(b0, b0);
        sh_ro[t] = pk2(b1, b1);
    }
    __syncthreads();

    // Load y (16 floats per thread) and scatter into pair arrays.
    // xp[j] = y[j-63]; thread t owns y[16t..16t+15] -> xp[63+16t .. 78+16t].
    float v[16];
    {
        const float4* y4 = reinterpret_cast<const float4*>(yr + 16 * t);
#pragma unroll
        for (int i = 0; i < 4; i++) {
            float4 f = __ldg(y4 + i);
            v[4 * i + 0] = f.x; v[4 * i + 1] = f.y;
            v[4 * i + 2] = f.z; v[4 * i + 3] = f.w;
        }
    }
#pragma unroll
    for (int i = 0; i < 8; i++)   // opairs[8t+31+i] = (v[2i], v[2i+1])
        sh_op[PIDX(31 + i, t)] = pk2(v[2 * i], v[2 * i + 1]);
#pragma unroll
    for (int i = 0; i < 7; i++)   // epairs[8t+32+i] = (v[2i+1], v[2i+2])
        sh_ep[PIDX(32 + i, t)] = pk2(v[2 * i + 1], v[2 * i + 2]);
    {
        float* epf = reinterpret_cast<float*>(sh_ep);
        epf[2 * PIDX(31, t) + 1] = v[0];    // hi of epairs[8t+31]
        epf[2 * PIDX(39, t) + 0] = v[15];   // lo of epairs[8t+39]
    }
    __syncthreads();

    // Stage 1: conv(y, h); residual pairs (reads only, before sync).
    ull acc[8];
    conv16(sh_ep, sh_op, sh_he, sh_ho, t, acc);

    ull r2[8];
    const ull neg1 = pk2(-1.0f, -1.0f);
#pragma unroll
    for (int q = 0; q < 8; q++) {
        ull yp = sh_op[PIDX(31 + q, t)];     // (y[16t+2q], y[16t+2q+1])
        r2[q] = fma2(acc[q], neg1, yp);       // resid = y - conv
    }
    __syncthreads();

    // Overwrite pair arrays with residual (identical padding geometry).
#pragma unroll
    for (int q = 0; q < 8; q++)
        sh_op[PIDX(31 + q, t)] = r2[q];
#pragma unroll
    for (int i = 0; i < 7; i++) {
        float a, b, c, d;
        unpk2(r2[i], a, b);
        unpk2(r2[i + 1], c, d);
        sh_ep[PIDX(32 + i, t)] = pk2(b, c);
    }
    {
        float* epf = reinterpret_cast<float*>(sh_ep);
        float a, b, c, d;
        unpk2(r2[0], a, b);
        epf[2 * PIDX(31, t) + 1] = a;
        unpk2(r2[7], c, d);
        epf[2 * PIDX(39, t) + 0] = d;
    }
    __syncthreads();

    // Stage 2: conv(resid, h_rev), then closed-form ISTA epilogue.
    conv16(sh_ep, sh_op, sh_re, sh_ro, t, acc);

    float xo[16];
#pragma unroll
    for (int q = 0; q < 8; q++) {
        float u0, u1;
        unpk2(acc[q], u0, u1);
        float a0 = s * u0;
        float a1 = s * u1;
        xo[2 * q + 0] = copysignf(TITER * fmaxf(fabsf(a0) - LAMBDA, 0.0f), a0);
        xo[2 * q + 1] = copysignf(TITER * fmaxf(fabsf(a1) - LAMBDA, 0.0f), a1);
    }
    float4* o4 = reinterpret_cast<float4*>(out + (long long)row * LDIM + 16 * t);
#pragma unroll
    for (int i = 0; i < 4; i++)
        o4[i] = make_float4(xo[4 * i], xo[4 * i + 1], xo[4 * i + 2], xo[4 * i + 3]);
}

extern "C" void kernel_launch(void* const* d_in, const int* in_sizes, int n_in,
                              void* d_out, int out_size)
{
    const float* y = nullptr;
    const float* h = nullptr;
    const float* s = nullptr;
    for (int i = 0; i < n_in; i++) {
        if (in_sizes[i] == BDIM * LDIM)      y = (const float*)d_in[i];
        else if (in_sizes[i] == KW)          h = (const float*)d_in[i];
        else if (in_sizes[i] == 1)           s = (const float*)d_in[i];
    }
    ista_row_kernel<<<BDIM, NTH>>>(y, h, s, (float*)d_out);
}